// round 14
// baseline (speedup 1.0000x reference)
#include <cuda_runtime.h>
#include <cuda_bf16.h>
#include <cstdint>

// Problem constants
#define M_TOTAL 8192   // B*S
#define K_TOTAL 4096   // IN_F
#define N_TOTAL 4096   // OUT_F

// GEMM tiling (bf16 HMMA), 2 CTAs/SM
#define BM 128
#define BN 128
#define BKE 64                        // K elems (bf16) per main-loop tile
#define BKB 128                       // K bytes per tile row (64 bf16)
#define KT (K_TOTAL / BKE)            // 64
#define P 144                         // padded smem row pitch (bytes)
#define A_SM (BM * P)                 // 18432
#define B_SM (BN * P)                 // 18432
#define STAGE (A_SM + B_SM)           // 36864
#define NSTAGE 3
#define SMEM_DYN (NSTAGE * STAGE)     // 110592  (x2 CTAs <= ~227KB)
#define A_CHUNKS (BM * BKB / 16)      // 1024
#define CHUNKS ((BM + BN) * BKB / 16) // 2048
#define KROWB (K_TOTAL * 2)           // global row bytes (bf16)
#define NTHREADS 128

// ---------------- device scratch ----------------------------------------------
__device__ unsigned int g_amax_bits;
__device__ __nv_bfloat16 g_xb[(size_t)M_TOTAL * K_TOTAL];
__device__ __nv_bfloat16 g_wb[(size_t)N_TOTAL * K_TOTAL];

// ---------------- helpers -------------------------------------------------------
__device__ __forceinline__ uint32_t smem_u32(const void* p) {
    uint32_t a;
    asm("{ .reg .u64 t; cvta.to.shared.u64 t, %1; cvt.u32.u64 %0, t; }"
        : "=r"(a) : "l"(p));
    return a;
}
__device__ __forceinline__ void cp_async16_s(uint32_t sdst, const void* gsrc) {
    asm volatile("cp.async.cg.shared.global [%0], [%1], 16;\n"
                 :: "r"(sdst), "l"(gsrc) : "memory");
}
__device__ __forceinline__ void ldsm_x4(uint32_t& r0, uint32_t& r1,
                                        uint32_t& r2, uint32_t& r3, uint32_t a) {
    asm volatile("ldmatrix.sync.aligned.m8n8.x4.shared.b16 {%0,%1,%2,%3}, [%4];"
                 : "=r"(r0), "=r"(r1), "=r"(r2), "=r"(r3) : "r"(a));
}
__device__ __forceinline__ void mma_bf16(float* c, const uint32_t* a,
                                         const uint32_t* b) {
    asm volatile(
        "mma.sync.aligned.m16n8k16.row.col.f32.bf16.bf16.f32 "
        "{%0,%1,%2,%3}, {%4,%5,%6,%7}, {%8,%9}, {%0,%1,%2,%3};"
        : "+f"(c[0]), "+f"(c[1]), "+f"(c[2]), "+f"(c[3])
        : "r"(a[0]), "r"(a[1]), "r"(a[2]), "r"(a[3]), "r"(b[0]), "r"(b[1]));
}
// epilogue: replicate bf16(bf16(i32) * bf16(scale)) exactly (validated R2)
__device__ __forceinline__ float dequant_one(float accf, float csf) {
    float v = __bfloat162float(__float2bfloat16(accf));
    return __bfloat162float(__float2bfloat16(v * csf));
}

// ---------------- kernel 1: pack w (int32 -> bf16) + reset amax -------------------
__global__ void packw_kernel(const int* __restrict__ w32, int n4) {
    if (blockIdx.x == 0 && threadIdx.x == 0) g_amax_bits = 0u;
    const int4* w4 = (const int4*)w32;
    uint2* q4 = (uint2*)g_wb;
    const int stride = gridDim.x * blockDim.x;
    int i = blockIdx.x * blockDim.x + threadIdx.x;
    for (; i + stride < n4; i += 2 * stride) {
        int4 v0 = __ldcs(w4 + i);
        int4 v1 = __ldcs(w4 + i + stride);
        __nv_bfloat162 l0 = __floats2bfloat162_rn((float)v0.x, (float)v0.y);
        __nv_bfloat162 h0 = __floats2bfloat162_rn((float)v0.z, (float)v0.w);
        __nv_bfloat162 l1 = __floats2bfloat162_rn((float)v1.x, (float)v1.y);
        __nv_bfloat162 h1 = __floats2bfloat162_rn((float)v1.z, (float)v1.w);
        uint2 o0, o1;
        o0.x = *(uint32_t*)&l0; o0.y = *(uint32_t*)&h0;
        o1.x = *(uint32_t*)&l1; o1.y = *(uint32_t*)&h1;
        __stcs(q4 + i, o0);
        __stcs(q4 + i + stride, o1);
    }
    for (; i < n4; i += stride) {
        int4 v = __ldcs(w4 + i);
        __nv_bfloat162 lo = __floats2bfloat162_rn((float)v.x, (float)v.y);
        __nv_bfloat162 hi = __floats2bfloat162_rn((float)v.z, (float)v.w);
        uint2 o;
        o.x = *(uint32_t*)&lo; o.y = *(uint32_t*)&hi;
        __stcs(q4 + i, o);
    }
}

// ---------------- kernel 2: global abs-max over x --------------------------------
__global__ void amax_kernel(const float* __restrict__ x, int n4) {
    const float4* x4 = (const float4*)x;
    const int stride = gridDim.x * blockDim.x;
    float m = 0.f;
    int i = blockIdx.x * blockDim.x + threadIdx.x;
    for (; i + stride < n4; i += 2 * stride) {
        float4 v0 = __ldcs(x4 + i);
        float4 v1 = __ldcs(x4 + i + stride);
        m = fmaxf(m, fmaxf(fmaxf(fabsf(v0.x), fabsf(v0.y)),
                           fmaxf(fabsf(v0.z), fabsf(v0.w))));
        m = fmaxf(m, fmaxf(fmaxf(fabsf(v1.x), fabsf(v1.y)),
                           fmaxf(fabsf(v1.z), fabsf(v1.w))));
    }
    for (; i < n4; i += stride) {
        float4 v = __ldcs(x4 + i);
        m = fmaxf(m, fmaxf(fmaxf(fabsf(v.x), fabsf(v.y)),
                           fmaxf(fabsf(v.z), fabsf(v.w))));
    }
    #pragma unroll
    for (int o = 16; o; o >>= 1) m = fmaxf(m, __shfl_xor_sync(0xffffffffu, m, o));
    __shared__ float s[32];
    int lane = threadIdx.x & 31, w = threadIdx.x >> 5;
    if (lane == 0) s[w] = m;
    __syncthreads();
    if (w == 0) {
        m = (lane < (int)(blockDim.x >> 5)) ? s[lane] : 0.f;
        #pragma unroll
        for (int o = 16; o; o >>= 1) m = fmaxf(m, __shfl_xor_sync(0xffffffffu, m, o));
        if (lane == 0) atomicMax(&g_amax_bits, __float_as_uint(m));
    }
}

// ---------------- kernel 3: quantize x -> int8-valued bf16 -----------------------
__global__ void quant_kernel(const float* __restrict__ x, int n4) {
    float amax = __uint_as_float(g_amax_bits);
    float scale = (amax == 0.f) ? 1.f : __fdiv_rn(amax, 127.f);
    const float4* x4 = (const float4*)x;
    uint2* q4 = (uint2*)g_xb;
    const int stride = gridDim.x * blockDim.x;

    auto q1 = [&](float4 v) -> uint2 {
        int a = __float2int_rn(__fdiv_rn(v.x, scale));
        int b = __float2int_rn(__fdiv_rn(v.y, scale));
        int c = __float2int_rn(__fdiv_rn(v.z, scale));
        int d = __float2int_rn(__fdiv_rn(v.w, scale));
        a = max(-127, min(127, a)); b = max(-127, min(127, b));
        c = max(-127, min(127, c)); d = max(-127, min(127, d));
        __nv_bfloat162 lo = __floats2bfloat162_rn((float)a, (float)b);
        __nv_bfloat162 hi = __floats2bfloat162_rn((float)c, (float)d);
        uint2 o;
        o.x = *(uint32_t*)&lo; o.y = *(uint32_t*)&hi;
        return o;
    };

    int i = blockIdx.x * blockDim.x + threadIdx.x;
    for (; i + stride < n4; i += 2 * stride) {
        float4 v0 = __ldcs(x4 + i);
        float4 v1 = __ldcs(x4 + i + stride);
        __stcs(q4 + i, q1(v0));
        __stcs(q4 + i + stride, q1(v1));
    }
    for (; i < n4; i += stride) {
        __stcs(q4 + i, q1(__ldcs(x4 + i)));
    }
}

// ---------------- kernel 4: bf16 GEMM (ldmatrix + HMMA, de-phased warps) ---------
__global__ __launch_bounds__(NTHREADS, 2)
void gemm_kernel(const float* __restrict__ w_scale_p,
                 const float* __restrict__ bias,
                 float* __restrict__ out) {
    extern __shared__ __align__(128) int8_t smem_raw[];
    const uint32_t sbase = smem_u32(smem_raw);

    const int tid = threadIdx.x;
    const int lane = tid & 31;
    const int wid = tid >> 5;            // 0..3
    const int bm = blockIdx.y, bn = blockIdx.x;

    const int wm = (wid & 1) * 64;       // 0 or 64  (M)
    const int wn = (wid >> 1) * 64;      // 0 or 64  (N)

    const int8_t* Ag = (const int8_t*)g_xb + (size_t)bm * BM * KROWB;
    const int8_t* Bg = (const int8_t*)g_wb + (size_t)bn * BN * KROWB;

    // per-lane ldmatrix offsets (b16 fragment geometry)
    const uint32_t aoff = (uint32_t)(lane & 15) * P + ((lane >> 4) << 4);
    const uint32_t boff = (uint32_t)((lane & 7) + ((lane >> 4) & 1) * 8) * P +
                          (((lane >> 3) & 1) << 4);

    float acc[4][8][4];
    #pragma unroll
    for (int mt = 0; mt < 4; ++mt)
        #pragma unroll
        for (int nt = 0; nt < 8; ++nt)
            #pragma unroll
            for (int i = 0; i < 4; ++i) acc[mt][nt][i] = 0.f;

    auto issue_stage = [&](int kt) {
        const uint32_t stg = sbase + (uint32_t)(kt % NSTAGE) * STAGE;
        #pragma unroll
        for (int it = 0; it < CHUNKS / NTHREADS; ++it) {
            int i = tid + it * NTHREADS;
            if (i < A_CHUNKS) {
                int row = i >> 3, c = (i & 7) << 4;
                cp_async16_s(stg + row * P + c,
                             Ag + (size_t)row * KROWB + kt * BKB + c);
            } else {
                int j = i - A_CHUNKS;
                int row = j >> 3, c = (j & 7) << 4;
                cp_async16_s(stg + A_SM + row * P + c,
                             Bg + (size_t)row * KROWB + kt * BKB + c);
            }
        }
        asm volatile("cp.async.commit_group;\n" ::: "memory");
    };

    issue_stage(0);
    issue_stage(1);

    for (int kt = 0; kt < KT; ++kt) {
        if (kt < KT - 1)
            asm volatile("cp.async.wait_group 1;\n" ::: "memory");
        else
            asm volatile("cp.async.wait_group 0;\n" ::: "memory");
        __syncthreads();

        const uint32_t stg = sbase + (uint32_t)(kt % NSTAGE) * STAGE;
        const uint32_t abase = stg + (uint32_t)wm * P + aoff;
        const uint32_t bbase = stg + A_SM + (uint32_t)wn * P + boff;

        #pragma unroll
        for (int ksi = 0; ksi < 4; ++ksi) {
            // de-phase: each warp walks the 4 k-steps in a rotated order so
            // LDSM bursts of different warps never coincide (fp32 accum of
            // small integers is exact -> order-independent)
            const int ks = (ksi + wid) & 3;
            const uint32_t kb = (uint32_t)ks * 32;
            uint32_t afr[4][4];
            #pragma unroll
            for (int mt = 0; mt < 4; ++mt)
                ldsm_x4(afr[mt][0], afr[mt][1], afr[mt][2], afr[mt][3],
                        abase + (uint32_t)(mt * 16) * P + kb);
            uint32_t bfr[8][2];
            #pragma unroll
            for (int ntpi = 0; ntpi < 4; ++ntpi) {
                // rotate B pair order per warp too (address spread in slot 0)
                const int ntp = (ntpi + wid) & 3;
                ldsm_x4(bfr[2 * ntp][0], bfr[2 * ntp][1],
                        bfr[2 * ntp + 1][0], bfr[2 * ntp + 1][1],
                        bbase + (uint32_t)(ntp * 16) * P + kb);
            }
            #pragma unroll
            for (int mt = 0; mt < 4; ++mt)
                #pragma unroll
                for (int nt = 0; nt < 8; ++nt)
                    mma_bf16(acc[mt][nt], afr[mt], bfr[nt]);

            // staggered next-stage issue: warp w drains its STS burst in slot
            // ksi==w, so at any k-step only one warp touches the store path
            if (ksi == wid && kt + 2 < KT) issue_stage(kt + 2);
        }
    }

    // ---- epilogue ----
    float amax = __uint_as_float(g_amax_bits);
    float xs = (amax == 0.f) ? 1.f : __fdiv_rn(amax, 127.f);
    float csf = __bfloat162float(__float2bfloat16(xs * w_scale_p[0]));

    #pragma unroll
    for (int mt = 0; mt < 4; ++mt) {
        #pragma unroll
        for (int nt = 0; nt < 8; ++nt) {
            int m0 = bm * BM + wm + mt * 16 + (lane >> 2);
            int n0 = bn * BN + wn + nt * 8 + (lane & 3) * 2;
            float b0 = __ldg(bias + n0);
            float b1 = __ldg(bias + n0 + 1);
            float2 r0, r1;
            r0.x = dequant_one(acc[mt][nt][0], csf) + b0;
            r0.y = dequant_one(acc[mt][nt][1], csf) + b1;
            r1.x = dequant_one(acc[mt][nt][2], csf) + b0;
            r1.y = dequant_one(acc[mt][nt][3], csf) + b1;
            *(float2*)&out[(size_t)m0 * N_TOTAL + n0] = r0;
            *(float2*)&out[(size_t)(m0 + 8) * N_TOTAL + n0] = r1;
        }
    }
}

// ---------------- launcher ----------------------------------------------------------
extern "C" void kernel_launch(void* const* d_in, const int* in_sizes, int n_in,
                              void* d_out, int out_size) {
    const float* x = (const float*)d_in[0];       // [4,2048,4096] fp32
    const int* w32 = (const int*)d_in[1];         // [4096,4096] int8-as-int32
    const float* wscale = (const float*)d_in[2];  // scalar fp32
    const float* bias = (const float*)d_in[3];    // [4096] fp32
    float* out = (float*)d_out;                   // fp32

    const int n4x = (M_TOTAL * K_TOTAL) / 4;
    const int n4w = (N_TOTAL * K_TOTAL) / 4;

    // order: packw (fused amax reset) -> amax -> quant -> gemm
    packw_kernel<<<1184, 512>>>(w32, n4w);
    amax_kernel<<<1184, 512>>>(x, n4x);
    quant_kernel<<<1184, 512>>>(x, n4x);

    cudaFuncSetAttribute(gemm_kernel, cudaFuncAttributeMaxDynamicSharedMemorySize,
                         SMEM_DYN);
    dim3 grid(N_TOTAL / BN, M_TOTAL / BM);
    gemm_kernel<<<grid, NTHREADS, SMEM_DYN>>>(wscale, bias, out);
}

// round 15
// speedup vs baseline: 1.4943x; 1.4943x over previous
#include <cuda_runtime.h>
#include <cuda_bf16.h>
#include <cstdint>

// Problem constants
#define M_TOTAL 8192   // B*S
#define K_TOTAL 4096   // IN_F
#define N_TOTAL 4096   // OUT_F

// GEMM tiling (bf16 HMMA), 2 CTAs/SM
#define BM 128
#define BN 128
#define BKE 64                        // K elems (bf16) per main-loop tile
#define BKB 128                       // K bytes per tile row (64 bf16)
#define KT (K_TOTAL / BKE)            // 64
#define P 144                         // padded smem row pitch (bytes)
#define A_SM (BM * P)                 // 18432
#define B_SM (BN * P)                 // 18432
#define STAGE (A_SM + B_SM)           // 36864
#define NSTAGE 3
#define SMEM_DYN (NSTAGE * STAGE)     // 110592  (x2 CTAs <= ~227KB)
#define A_CHUNKS (BM * BKB / 16)      // 1024
#define CHUNKS ((BM + BN) * BKB / 16) // 2048
#define KROWB (K_TOTAL * 2)           // global row bytes (bf16)
#define NTHREADS 128

// ---------------- device scratch ----------------------------------------------
__device__ unsigned int g_amax_bits;
__device__ __nv_bfloat16 g_xb[(size_t)M_TOTAL * K_TOTAL];
__device__ __nv_bfloat16 g_wb[(size_t)N_TOTAL * K_TOTAL];

// ---------------- helpers -------------------------------------------------------
__device__ __forceinline__ uint32_t smem_u32(const void* p) {
    uint32_t a;
    asm("{ .reg .u64 t; cvta.to.shared.u64 t, %1; cvt.u32.u64 %0, t; }"
        : "=r"(a) : "l"(p));
    return a;
}
__device__ __forceinline__ void cp_async16_s(uint32_t sdst, const void* gsrc) {
    asm volatile("cp.async.cg.shared.global [%0], [%1], 16;\n"
                 :: "r"(sdst), "l"(gsrc) : "memory");
}
__device__ __forceinline__ void ldsm_x4(uint32_t& r0, uint32_t& r1,
                                        uint32_t& r2, uint32_t& r3, uint32_t a) {
    asm volatile("ldmatrix.sync.aligned.m8n8.x4.shared.b16 {%0,%1,%2,%3}, [%4];"
                 : "=r"(r0), "=r"(r1), "=r"(r2), "=r"(r3) : "r"(a));
}
__device__ __forceinline__ void mma_bf16(float* c, const uint32_t* a,
                                         const uint32_t* b) {
    asm volatile(
        "mma.sync.aligned.m16n8k16.row.col.f32.bf16.bf16.f32 "
        "{%0,%1,%2,%3}, {%4,%5,%6,%7}, {%8,%9}, {%0,%1,%2,%3};"
        : "+f"(c[0]), "+f"(c[1]), "+f"(c[2]), "+f"(c[3])
        : "r"(a[0]), "r"(a[1]), "r"(a[2]), "r"(a[3]), "r"(b[0]), "r"(b[1]));
}
// epilogue: replicate bf16(bf16(i32) * bf16(scale)) exactly (validated R2)
__device__ __forceinline__ float dequant_one(float accf, float csf) {
    float v = __bfloat162float(__float2bfloat16(accf));
    return __bfloat162float(__float2bfloat16(v * csf));
}

// ---------------- kernel 1: pack w (int32 -> bf16) + reset amax -------------------
__global__ void packw_kernel(const int* __restrict__ w32, int n4) {
    if (blockIdx.x == 0 && threadIdx.x == 0) g_amax_bits = 0u;
    const int4* w4 = (const int4*)w32;
    uint2* q4 = (uint2*)g_wb;
    const int stride = gridDim.x * blockDim.x;
    int i = blockIdx.x * blockDim.x + threadIdx.x;
    for (; i + stride < n4; i += 2 * stride) {
        int4 v0 = __ldcs(w4 + i);
        int4 v1 = __ldcs(w4 + i + stride);
        __nv_bfloat162 l0 = __floats2bfloat162_rn((float)v0.x, (float)v0.y);
        __nv_bfloat162 h0 = __floats2bfloat162_rn((float)v0.z, (float)v0.w);
        __nv_bfloat162 l1 = __floats2bfloat162_rn((float)v1.x, (float)v1.y);
        __nv_bfloat162 h1 = __floats2bfloat162_rn((float)v1.z, (float)v1.w);
        uint2 o0, o1;
        o0.x = *(uint32_t*)&l0; o0.y = *(uint32_t*)&h0;
        o1.x = *(uint32_t*)&l1; o1.y = *(uint32_t*)&h1;
        __stcs(q4 + i, o0);
        __stcs(q4 + i + stride, o1);
    }
    for (; i < n4; i += stride) {
        int4 v = __ldcs(w4 + i);
        __nv_bfloat162 lo = __floats2bfloat162_rn((float)v.x, (float)v.y);
        __nv_bfloat162 hi = __floats2bfloat162_rn((float)v.z, (float)v.w);
        uint2 o;
        o.x = *(uint32_t*)&lo; o.y = *(uint32_t*)&hi;
        __stcs(q4 + i, o);
    }
}

// ---------------- kernel 2: global abs-max over x --------------------------------
__global__ void amax_kernel(const float* __restrict__ x, int n4) {
    const float4* x4 = (const float4*)x;
    const int stride = gridDim.x * blockDim.x;
    float m = 0.f;
    int i = blockIdx.x * blockDim.x + threadIdx.x;
    for (; i + stride < n4; i += 2 * stride) {
        float4 v0 = __ldcs(x4 + i);
        float4 v1 = __ldcs(x4 + i + stride);
        m = fmaxf(m, fmaxf(fmaxf(fabsf(v0.x), fabsf(v0.y)),
                           fmaxf(fabsf(v0.z), fabsf(v0.w))));
        m = fmaxf(m, fmaxf(fmaxf(fabsf(v1.x), fabsf(v1.y)),
                           fmaxf(fabsf(v1.z), fabsf(v1.w))));
    }
    for (; i < n4; i += stride) {
        float4 v = __ldcs(x4 + i);
        m = fmaxf(m, fmaxf(fmaxf(fabsf(v.x), fabsf(v.y)),
                           fmaxf(fabsf(v.z), fabsf(v.w))));
    }
    #pragma unroll
    for (int o = 16; o; o >>= 1) m = fmaxf(m, __shfl_xor_sync(0xffffffffu, m, o));
    __shared__ float s[32];
    int lane = threadIdx.x & 31, w = threadIdx.x >> 5;
    if (lane == 0) s[w] = m;
    __syncthreads();
    if (w == 0) {
        m = (lane < (int)(blockDim.x >> 5)) ? s[lane] : 0.f;
        #pragma unroll
        for (int o = 16; o; o >>= 1) m = fmaxf(m, __shfl_xor_sync(0xffffffffu, m, o));
        if (lane == 0) atomicMax(&g_amax_bits, __float_as_uint(m));
    }
}

// ---------------- kernel 3: quantize x -> int8-valued bf16 -----------------------
__global__ void quant_kernel(const float* __restrict__ x, int n4) {
    float amax = __uint_as_float(g_amax_bits);
    float scale = (amax == 0.f) ? 1.f : __fdiv_rn(amax, 127.f);
    const float4* x4 = (const float4*)x;
    uint2* q4 = (uint2*)g_xb;
    const int stride = gridDim.x * blockDim.x;

    auto q1 = [&](float4 v) -> uint2 {
        int a = __float2int_rn(__fdiv_rn(v.x, scale));
        int b = __float2int_rn(__fdiv_rn(v.y, scale));
        int c = __float2int_rn(__fdiv_rn(v.z, scale));
        int d = __float2int_rn(__fdiv_rn(v.w, scale));
        a = max(-127, min(127, a)); b = max(-127, min(127, b));
        c = max(-127, min(127, c)); d = max(-127, min(127, d));
        __nv_bfloat162 lo = __floats2bfloat162_rn((float)a, (float)b);
        __nv_bfloat162 hi = __floats2bfloat162_rn((float)c, (float)d);
        uint2 o;
        o.x = *(uint32_t*)&lo; o.y = *(uint32_t*)&hi;
        return o;
    };

    int i = blockIdx.x * blockDim.x + threadIdx.x;
    for (; i + stride < n4; i += 2 * stride) {
        float4 v0 = __ldcs(x4 + i);
        float4 v1 = __ldcs(x4 + i + stride);
        __stcs(q4 + i, q1(v0));
        __stcs(q4 + i + stride, q1(v1));
    }
    for (; i < n4; i += stride) {
        __stcs(q4 + i, q1(__ldcs(x4 + i)));
    }
}

// ---------------- kernel 4: bf16 GEMM (R13 mainloop, verbatim) -------------------
__global__ __launch_bounds__(NTHREADS, 2)
void gemm_kernel(const float* __restrict__ w_scale_p,
                 const float* __restrict__ bias,
                 float* __restrict__ out) {
    extern __shared__ __align__(128) int8_t smem_raw[];
    const uint32_t sbase = smem_u32(smem_raw);

    const int tid = threadIdx.x;
    const int lane = tid & 31;
    const int wid = tid >> 5;            // 0..3
    const int bm = blockIdx.y, bn = blockIdx.x;

    const int wm = (wid & 1) * 64;       // 0 or 64  (M)
    const int wn = (wid >> 1) * 64;      // 0 or 64  (N)

    const int8_t* Ag = (const int8_t*)g_xb + (size_t)bm * BM * KROWB;
    const int8_t* Bg = (const int8_t*)g_wb + (size_t)bn * BN * KROWB;

    // per-lane ldmatrix offsets (b16 fragment geometry)
    const uint32_t aoff = (uint32_t)(lane & 15) * P + ((lane >> 4) << 4);
    const uint32_t boff = (uint32_t)((lane & 7) + ((lane >> 4) & 1) * 8) * P +
                          (((lane >> 3) & 1) << 4);

    float acc[4][8][4];
    #pragma unroll
    for (int mt = 0; mt < 4; ++mt)
        #pragma unroll
        for (int nt = 0; nt < 8; ++nt)
            #pragma unroll
            for (int i = 0; i < 4; ++i) acc[mt][nt][i] = 0.f;

    auto issue_stage = [&](int kt) {
        const uint32_t stg = sbase + (uint32_t)(kt % NSTAGE) * STAGE;
        #pragma unroll
        for (int it = 0; it < CHUNKS / NTHREADS; ++it) {
            int i = tid + it * NTHREADS;
            if (i < A_CHUNKS) {
                int row = i >> 3, c = (i & 7) << 4;
                cp_async16_s(stg + row * P + c,
                             Ag + (size_t)row * KROWB + kt * BKB + c);
            } else {
                int j = i - A_CHUNKS;
                int row = j >> 3, c = (j & 7) << 4;
                cp_async16_s(stg + A_SM + row * P + c,
                             Bg + (size_t)row * KROWB + kt * BKB + c);
            }
        }
        asm volatile("cp.async.commit_group;\n" ::: "memory");
    };

    issue_stage(0);
    issue_stage(1);

    for (int kt = 0; kt < KT; ++kt) {
        if (kt < KT - 1)
            asm volatile("cp.async.wait_group 1;\n" ::: "memory");
        else
            asm volatile("cp.async.wait_group 0;\n" ::: "memory");
        __syncthreads();

        const uint32_t stg = sbase + (uint32_t)(kt % NSTAGE) * STAGE;
        const uint32_t abase = stg + (uint32_t)wm * P + aoff;
        const uint32_t bbase = stg + A_SM + (uint32_t)wn * P + boff;

        #pragma unroll
        for (int ksi = 0; ksi < 4; ++ksi) {
            // de-phase: each warp walks the 4 k-steps in a rotated order so
            // LDSM bursts of different warps never coincide (fp32 accum of
            // small integers is exact -> order-independent)
            const int ks = (ksi + wid) & 3;
            const uint32_t kb = (uint32_t)ks * 32;
            uint32_t afr[4][4];
            #pragma unroll
            for (int mt = 0; mt < 4; ++mt)
                ldsm_x4(afr[mt][0], afr[mt][1], afr[mt][2], afr[mt][3],
                        abase + (uint32_t)(mt * 16) * P + kb);
            uint32_t bfr[8][2];
            #pragma unroll
            for (int ntp = 0; ntp < 4; ++ntp)
                ldsm_x4(bfr[2 * ntp][0], bfr[2 * ntp][1],
                        bfr[2 * ntp + 1][0], bfr[2 * ntp + 1][1],
                        bbase + (uint32_t)(ntp * 16) * P + kb);
            #pragma unroll
            for (int mt = 0; mt < 4; ++mt)
                #pragma unroll
                for (int nt = 0; nt < 8; ++nt)
                    mma_bf16(acc[mt][nt], afr[mt], bfr[nt]);

            // staggered next-stage issue: warp w drains its STS burst in slot
            // ksi==w, so at any k-step only one warp touches the store path
            if (ksi == wid && kt + 2 < KT) issue_stage(kt + 2);
        }
    }

    // ---- epilogue ----
    float amax = __uint_as_float(g_amax_bits);
    float xs = (amax == 0.f) ? 1.f : __fdiv_rn(amax, 127.f);
    float csf = __bfloat162float(__float2bfloat16(xs * w_scale_p[0]));

    #pragma unroll
    for (int mt = 0; mt < 4; ++mt) {
        #pragma unroll
        for (int nt = 0; nt < 8; ++nt) {
            int m0 = bm * BM + wm + mt * 16 + (lane >> 2);
            int n0 = bn * BN + wn + nt * 8 + (lane & 3) * 2;
            float b0 = __ldg(bias + n0);
            float b1 = __ldg(bias + n0 + 1);
            float2 r0, r1;
            r0.x = dequant_one(acc[mt][nt][0], csf) + b0;
            r0.y = dequant_one(acc[mt][nt][1], csf) + b1;
            r1.x = dequant_one(acc[mt][nt][2], csf) + b0;
            r1.y = dequant_one(acc[mt][nt][3], csf) + b1;
            *(float2*)&out[(size_t)m0 * N_TOTAL + n0] = r0;
            *(float2*)&out[(size_t)(m0 + 8) * N_TOTAL + n0] = r1;
        }
    }
}

// ---------------- launcher ----------------------------------------------------------
extern "C" void kernel_launch(void* const* d_in, const int* in_sizes, int n_in,
                              void* d_out, int out_size) {
    const float* x = (const float*)d_in[0];       // [4,2048,4096] fp32
    const int* w32 = (const int*)d_in[1];         // [4096,4096] int8-as-int32
    const float* wscale = (const float*)d_in[2];  // scalar fp32
    const float* bias = (const float*)d_in[3];    // [4096] fp32
    float* out = (float*)d_out;                   // fp32

    const int n4x = (M_TOTAL * K_TOTAL) / 4;
    const int n4w = (N_TOTAL * K_TOTAL) / 4;

    // order: packw (fused amax reset) -> amax -> quant -> gemm
    packw_kernel<<<1184, 512>>>(w32, n4w);
    amax_kernel<<<1184, 512>>>(x, n4x);
    quant_kernel<<<1184, 512>>>(x, n4x);

    cudaFuncSetAttribute(gemm_kernel, cudaFuncAttributeMaxDynamicSharedMemorySize,
                         SMEM_DYN);
    dim3 grid(N_TOTAL / BN, M_TOTAL / BM);
    gemm_kernel<<<grid, NTHREADS, SMEM_DYN>>>(wscale, bias, out);
}

// round 16
// speedup vs baseline: 1.5488x; 1.0364x over previous
#include <cuda_runtime.h>
#include <cuda_bf16.h>
#include <cstdint>

// Problem constants
#define M_TOTAL 8192   // B*S
#define K_TOTAL 4096   // IN_F
#define N_TOTAL 4096   // OUT_F

// GEMM tiling (bf16 HMMA), 2 CTAs/SM
#define BM 128
#define BN 128
#define BKE 64                        // K elems (bf16) per main-loop tile
#define BKB 128                       // K bytes per tile row (64 bf16)
#define KT (K_TOTAL / BKE)            // 64
#define P 144                         // padded smem row pitch (bytes)
#define A_SM (BM * P)                 // 18432
#define B_SM (BN * P)                 // 18432
#define STAGE (A_SM + B_SM)           // 36864
#define NSTAGE 3
#define SMEM_DYN (NSTAGE * STAGE)     // 110592  (x2 CTAs <= ~227KB)
#define A_CHUNKS (BM * BKB / 16)      // 1024
#define CHUNKS ((BM + BN) * BKB / 16) // 2048
#define KROWB (K_TOTAL * 2)           // global row bytes (bf16)
#define NTHREADS 128

// ---------------- device scratch ----------------------------------------------
__device__ unsigned int g_amax_bits;
__device__ __nv_bfloat16 g_xb[(size_t)M_TOTAL * K_TOTAL];
__device__ __nv_bfloat16 g_wb[(size_t)N_TOTAL * K_TOTAL];

// ---------------- helpers -------------------------------------------------------
__device__ __forceinline__ uint32_t smem_u32(const void* p) {
    uint32_t a;
    asm("{ .reg .u64 t; cvta.to.shared.u64 t, %1; cvt.u32.u64 %0, t; }"
        : "=r"(a) : "l"(p));
    return a;
}
__device__ __forceinline__ void cp_async16_s(uint32_t sdst, const void* gsrc) {
    asm volatile("cp.async.cg.shared.global [%0], [%1], 16;\n"
                 :: "r"(sdst), "l"(gsrc) : "memory");
}
__device__ __forceinline__ void ldsm_x4(uint32_t& r0, uint32_t& r1,
                                        uint32_t& r2, uint32_t& r3, uint32_t a) {
    asm volatile("ldmatrix.sync.aligned.m8n8.x4.shared.b16 {%0,%1,%2,%3}, [%4];"
                 : "=r"(r0), "=r"(r1), "=r"(r2), "=r"(r3) : "r"(a));
}
__device__ __forceinline__ void mma_bf16(float* c, const uint32_t* a,
                                         const uint32_t* b) {
    asm volatile(
        "mma.sync.aligned.m16n8k16.row.col.f32.bf16.bf16.f32 "
        "{%0,%1,%2,%3}, {%4,%5,%6,%7}, {%8,%9}, {%0,%1,%2,%3};"
        : "+f"(c[0]), "+f"(c[1]), "+f"(c[2]), "+f"(c[3])
        : "r"(a[0]), "r"(a[1]), "r"(a[2]), "r"(a[3]), "r"(b[0]), "r"(b[1]));
}
// epilogue: replicate bf16(bf16(i32) * bf16(scale)) exactly (validated R2)
__device__ __forceinline__ float dequant_one(float accf, float csf) {
    float v = __bfloat162float(__float2bfloat16(accf));
    return __bfloat162float(__float2bfloat16(v * csf));
}

// ---------------- kernel 1: pack w (int32 -> bf16) + reset amax -------------------
__global__ void packw_kernel(const int* __restrict__ w32, int n4) {
    if (blockIdx.x == 0 && threadIdx.x == 0) g_amax_bits = 0u;
    const int4* w4 = (const int4*)w32;
    uint2* q4 = (uint2*)g_wb;
    const int stride = gridDim.x * blockDim.x;
    int i = blockIdx.x * blockDim.x + threadIdx.x;
    for (; i + stride < n4; i += 2 * stride) {
        int4 v0 = __ldcs(w4 + i);
        int4 v1 = __ldcs(w4 + i + stride);
        __nv_bfloat162 l0 = __floats2bfloat162_rn((float)v0.x, (float)v0.y);
        __nv_bfloat162 h0 = __floats2bfloat162_rn((float)v0.z, (float)v0.w);
        __nv_bfloat162 l1 = __floats2bfloat162_rn((float)v1.x, (float)v1.y);
        __nv_bfloat162 h1 = __floats2bfloat162_rn((float)v1.z, (float)v1.w);
        uint2 o0, o1;
        o0.x = *(uint32_t*)&l0; o0.y = *(uint32_t*)&h0;
        o1.x = *(uint32_t*)&l1; o1.y = *(uint32_t*)&h1;
        __stcs(q4 + i, o0);
        __stcs(q4 + i + stride, o1);
    }
    for (; i < n4; i += stride) {
        int4 v = __ldcs(w4 + i);
        __nv_bfloat162 lo = __floats2bfloat162_rn((float)v.x, (float)v.y);
        __nv_bfloat162 hi = __floats2bfloat162_rn((float)v.z, (float)v.w);
        uint2 o;
        o.x = *(uint32_t*)&lo; o.y = *(uint32_t*)&hi;
        __stcs(q4 + i, o);
    }
}

// ---------------- kernel 2: global abs-max over x --------------------------------
__global__ void amax_kernel(const float* __restrict__ x, int n4) {
    const float4* x4 = (const float4*)x;
    const int stride = gridDim.x * blockDim.x;
    float m = 0.f;
    int i = blockIdx.x * blockDim.x + threadIdx.x;
    for (; i + stride < n4; i += 2 * stride) {
        float4 v0 = __ldcs(x4 + i);
        float4 v1 = __ldcs(x4 + i + stride);
        m = fmaxf(m, fmaxf(fmaxf(fabsf(v0.x), fabsf(v0.y)),
                           fmaxf(fabsf(v0.z), fabsf(v0.w))));
        m = fmaxf(m, fmaxf(fmaxf(fabsf(v1.x), fabsf(v1.y)),
                           fmaxf(fabsf(v1.z), fabsf(v1.w))));
    }
    for (; i < n4; i += stride) {
        float4 v = __ldcs(x4 + i);
        m = fmaxf(m, fmaxf(fmaxf(fabsf(v.x), fabsf(v.y)),
                           fmaxf(fabsf(v.z), fabsf(v.w))));
    }
    #pragma unroll
    for (int o = 16; o; o >>= 1) m = fmaxf(m, __shfl_xor_sync(0xffffffffu, m, o));
    __shared__ float s[32];
    int lane = threadIdx.x & 31, w = threadIdx.x >> 5;
    if (lane == 0) s[w] = m;
    __syncthreads();
    if (w == 0) {
        m = (lane < (int)(blockDim.x >> 5)) ? s[lane] : 0.f;
        #pragma unroll
        for (int o = 16; o; o >>= 1) m = fmaxf(m, __shfl_xor_sync(0xffffffffu, m, o));
        if (lane == 0) atomicMax(&g_amax_bits, __float_as_uint(m));
    }
}

// ---------------- kernel 3: quantize x -> int8-valued bf16 -----------------------
__global__ void quant_kernel(const float* __restrict__ x, int n4) {
    float amax = __uint_as_float(g_amax_bits);
    float scale = (amax == 0.f) ? 1.f : __fdiv_rn(amax, 127.f);
    const float4* x4 = (const float4*)x;
    uint2* q4 = (uint2*)g_xb;
    const int stride = gridDim.x * blockDim.x;

    auto q1 = [&](float4 v) -> uint2 {
        int a = __float2int_rn(__fdiv_rn(v.x, scale));
        int b = __float2int_rn(__fdiv_rn(v.y, scale));
        int c = __float2int_rn(__fdiv_rn(v.z, scale));
        int d = __float2int_rn(__fdiv_rn(v.w, scale));
        a = max(-127, min(127, a)); b = max(-127, min(127, b));
        c = max(-127, min(127, c)); d = max(-127, min(127, d));
        __nv_bfloat162 lo = __floats2bfloat162_rn((float)a, (float)b);
        __nv_bfloat162 hi = __floats2bfloat162_rn((float)c, (float)d);
        uint2 o;
        o.x = *(uint32_t*)&lo; o.y = *(uint32_t*)&hi;
        return o;
    };

    int i = blockIdx.x * blockDim.x + threadIdx.x;
    for (; i + stride < n4; i += 2 * stride) {
        float4 v0 = __ldcs(x4 + i);
        float4 v1 = __ldcs(x4 + i + stride);
        __stcs(q4 + i, q1(v0));
        __stcs(q4 + i + stride, q1(v1));
    }
    for (; i < n4; i += stride) {
        __stcs(q4 + i, q1(__ldcs(x4 + i)));
    }
}

// ---------------- kernel 4: bf16 GEMM (spread cp.async, de-phased warps) ---------
__global__ __launch_bounds__(NTHREADS, 2)
void gemm_kernel(const float* __restrict__ w_scale_p,
                 const float* __restrict__ bias,
                 float* __restrict__ out) {
    extern __shared__ __align__(128) int8_t smem_raw[];
    const uint32_t sbase = smem_u32(smem_raw);

    const int tid = threadIdx.x;
    const int lane = tid & 31;
    const int wid = tid >> 5;            // 0..3
    const int bm = blockIdx.y, bn = blockIdx.x;

    const int wm = (wid & 1) * 64;       // 0 or 64  (M)
    const int wn = (wid >> 1) * 64;      // 0 or 64  (N)

    const int8_t* Ag = (const int8_t*)g_xb + (size_t)bm * BM * KROWB;
    const int8_t* Bg = (const int8_t*)g_wb + (size_t)bn * BN * KROWB;

    // per-lane ldmatrix offsets (b16 fragment geometry)
    const uint32_t aoff = (uint32_t)(lane & 15) * P + ((lane >> 4) << 4);
    const uint32_t boff = (uint32_t)((lane & 7) + ((lane >> 4) & 1) * 8) * P +
                          (((lane >> 3) & 1) << 4);

    float acc[4][8][4];
    #pragma unroll
    for (int mt = 0; mt < 4; ++mt)
        #pragma unroll
        for (int nt = 0; nt < 8; ++nt)
            #pragma unroll
            for (int i = 0; i < 4; ++i) acc[mt][nt][i] = 0.f;

    // issue one chunk quarter (4 of this thread's 16 chunks) for stage kt
    auto issue_quarter = [&](int kt, int quarter) {
        const uint32_t stg = sbase + (uint32_t)(kt % NSTAGE) * STAGE;
        #pragma unroll
        for (int q = 0; q < 4; ++q) {
            int i = tid + (quarter * 4 + q) * NTHREADS;
            if (i < A_CHUNKS) {
                int row = i >> 3, c = (i & 7) << 4;
                cp_async16_s(stg + row * P + c,
                             Ag + (size_t)row * KROWB + kt * BKB + c);
            } else {
                int j = i - A_CHUNKS;
                int row = j >> 3, c = (j & 7) << 4;
                cp_async16_s(stg + A_SM + row * P + c,
                             Bg + (size_t)row * KROWB + kt * BKB + c);
            }
        }
    };
    auto issue_stage = [&](int kt) {
        #pragma unroll
        for (int qq = 0; qq < 4; ++qq) issue_quarter(kt, qq);
        asm volatile("cp.async.commit_group;\n" ::: "memory");
    };

    issue_stage(0);
    issue_stage(1);

    for (int kt = 0; kt < KT; ++kt) {
        if (kt < KT - 1)
            asm volatile("cp.async.wait_group 1;\n" ::: "memory");
        else
            asm volatile("cp.async.wait_group 0;\n" ::: "memory");
        __syncthreads();

        const uint32_t stg = sbase + (uint32_t)(kt % NSTAGE) * STAGE;
        const uint32_t abase = stg + (uint32_t)wm * P + aoff;
        const uint32_t bbase = stg + A_SM + (uint32_t)wn * P + boff;

        #pragma unroll
        for (int ksi = 0; ksi < 4; ++ksi) {
            // de-phase: each warp walks the 4 k-steps in a rotated order so
            // LDSM bursts of different warps never coincide (fp32 accum of
            // small integers is exact -> order-independent)
            const int ks = (ksi + wid) & 3;
            const uint32_t kb = (uint32_t)ks * 32;
            uint32_t afr[4][4];
            #pragma unroll
            for (int mt = 0; mt < 4; ++mt)
                ldsm_x4(afr[mt][0], afr[mt][1], afr[mt][2], afr[mt][3],
                        abase + (uint32_t)(mt * 16) * P + kb);
            uint32_t bfr[8][2];
            #pragma unroll
            for (int ntp = 0; ntp < 4; ++ntp)
                ldsm_x4(bfr[2 * ntp][0], bfr[2 * ntp][1],
                        bfr[2 * ntp + 1][0], bfr[2 * ntp + 1][1],
                        bbase + (uint32_t)(ntp * 16) * P + kb);

            // spread next-stage cp.async: 4 chunks per k-step (LSU drain rides
            // under the HMMA block instead of one 16-op burst per tile)
            if (kt + 2 < KT) {
                issue_quarter(kt + 2, ksi);
                if (ksi == 3)
                    asm volatile("cp.async.commit_group;\n" ::: "memory");
            }

            #pragma unroll
            for (int mt = 0; mt < 4; ++mt)
                #pragma unroll
                for (int nt = 0; nt < 8; ++nt)
                    mma_bf16(acc[mt][nt], afr[mt], bfr[nt]);
        }
    }

    // ---- epilogue ----
    float amax = __uint_as_float(g_amax_bits);
    float xs = (amax == 0.f) ? 1.f : __fdiv_rn(amax, 127.f);
    float csf = __bfloat162float(__float2bfloat16(xs * w_scale_p[0]));

    #pragma unroll
    for (int mt = 0; mt < 4; ++mt) {
        #pragma unroll
        for (int nt = 0; nt < 8; ++nt) {
            int m0 = bm * BM + wm + mt * 16 + (lane >> 2);
            int n0 = bn * BN + wn + nt * 8 + (lane & 3) * 2;
            float b0 = __ldg(bias + n0);
            float b1 = __ldg(bias + n0 + 1);
            float2 r0, r1;
            r0.x = dequant_one(acc[mt][nt][0], csf) + b0;
            r0.y = dequant_one(acc[mt][nt][1], csf) + b1;
            r1.x = dequant_one(acc[mt][nt][2], csf) + b0;
            r1.y = dequant_one(acc[mt][nt][3], csf) + b1;
            __stcs((float2*)&out[(size_t)m0 * N_TOTAL + n0], r0);
            __stcs((float2*)&out[(size_t)(m0 + 8) * N_TOTAL + n0], r1);
        }
    }
}

// ---------------- launcher ----------------------------------------------------------
extern "C" void kernel_launch(void* const* d_in, const int* in_sizes, int n_in,
                              void* d_out, int out_size) {
    const float* x = (const float*)d_in[0];       // [4,2048,4096] fp32
    const int* w32 = (const int*)d_in[1];         // [4096,4096] int8-as-int32
    const float* wscale = (const float*)d_in[2];  // scalar fp32
    const float* bias = (const float*)d_in[3];    // [4096] fp32
    float* out = (float*)d_out;                   // fp32

    const int n4x = (M_TOTAL * K_TOTAL) / 4;
    const int n4w = (N_TOTAL * K_TOTAL) / 4;

    // order: packw (fused amax reset) -> amax -> quant -> gemm
    packw_kernel<<<1184, 512>>>(w32, n4w);
    amax_kernel<<<1184, 512>>>(x, n4x);
    quant_kernel<<<1184, 512>>>(x, n4x);

    cudaFuncSetAttribute(gemm_kernel, cudaFuncAttributeMaxDynamicSharedMemorySize,
                         SMEM_DYN);
    dim3 grid(N_TOTAL / BN, M_TOTAL / BM);
    gemm_kernel<<<grid, NTHREADS, SMEM_DYN>>>(wscale, bias, out);
}